// round 1
// baseline (speedup 1.0000x reference)
#include <cuda_runtime.h>
#include <math.h>

#define S_DIM 128
#define R_DIM 256
#define C_DIM 256
#define H_DIM 8
#define D_DIM 32
#define HD_DIM 256
#define SR_DIM (S_DIM * R_DIM)

// Scratch (device globals; allocation-free contract)
__device__ float g_Q[S_DIM * H_DIM * R_DIM * D_DIM];   // [s][h][r][d]
__device__ float g_K[S_DIM * H_DIM * R_DIM * D_DIM];
__device__ float g_V[S_DIM * H_DIM * R_DIM * D_DIM];
__device__ float g_G[S_DIM * H_DIM * R_DIM * D_DIM];
__device__ float g_O[S_DIM * H_DIM * R_DIM * D_DIM];
__device__ float g_biasT[H_DIM * R_DIM * R_DIM];       // [h][q][k]

// ---------------------------------------------------------------------------
// Kernel 1: bias [q][k][h] -> biasT [h][q][k]  (makes per-query bias reads
// contiguous in k; bias is s-independent and L2-resident thereafter)
// ---------------------------------------------------------------------------
__global__ void bias_transpose_kernel(const float* __restrict__ bias) {
    int idx = blockIdx.x * blockDim.x + threadIdx.x;
    if (idx < H_DIM * R_DIM * R_DIM) {
        int k  = idx & 255;
        int qq = (idx >> 8) & 255;
        int h  = idx >> 16;
        g_biasT[idx] = bias[((qq << 8) + k) * 8 + h];
    }
}

// ---------------------------------------------------------------------------
// Kernel 2: fused projections. type z: 0=Q(*norm) 1=K 2=V 3=G(sigmoid+b_g)
// C = A[SR,256] * W[256,256], 128x128 tile, k-chunk 8, 8x8 per thread.
// Output layout [s][h][r][d].
// ---------------------------------------------------------------------------
__global__ void proj_kernel(const float* __restrict__ qin,
                            const float* __restrict__ kvin,
                            const float* __restrict__ w_q,
                            const float* __restrict__ w_k,
                            const float* __restrict__ w_v,
                            const float* __restrict__ w_g,
                            const float* __restrict__ b_g) {
    __shared__ float As[8][128];
    __shared__ float Bs[8][128];
    int type = blockIdx.z;
    const float* A = (type == 1 || type == 2) ? kvin : qin;
    const float* W = (type == 0) ? w_q : (type == 1) ? w_k : (type == 2) ? w_v : w_g;
    float* Out = (type == 0) ? g_Q : (type == 1) ? g_K : (type == 2) ? g_V : g_G;

    int t = threadIdx.x;
    int bM = blockIdx.x * 128;
    int bN = blockIdx.y * 128;
    int tx = t & 15, ty = t >> 4;
    int arow = t >> 1, ak = (t & 1) * 4;
    int bk = t >> 5, bcol = (t & 31) * 4;

    float acc[8][8];
#pragma unroll
    for (int i = 0; i < 8; i++)
#pragma unroll
        for (int j = 0; j < 8; j++) acc[i][j] = 0.f;

    for (int k0 = 0; k0 < 256; k0 += 8) {
        float4 av = *(const float4*)&A[(bM + arow) * 256 + k0 + ak];
        float4 bv = *(const float4*)&W[(k0 + bk) * 256 + bN + bcol];
        __syncthreads();
        As[ak + 0][arow] = av.x;
        As[ak + 1][arow] = av.y;
        As[ak + 2][arow] = av.z;
        As[ak + 3][arow] = av.w;
        *(float4*)&Bs[bk][bcol] = bv;
        __syncthreads();
#pragma unroll
        for (int kk = 0; kk < 8; kk++) {
            float4 a0 = *(const float4*)&As[kk][ty * 8];
            float4 a1 = *(const float4*)&As[kk][ty * 8 + 4];
            float4 b0 = *(const float4*)&Bs[kk][tx * 8];
            float4 b1 = *(const float4*)&Bs[kk][tx * 8 + 4];
            float a[8] = {a0.x, a0.y, a0.z, a0.w, a1.x, a1.y, a1.z, a1.w};
            float b[8] = {b0.x, b0.y, b0.z, b0.w, b1.x, b1.y, b1.z, b1.w};
#pragma unroll
            for (int i = 0; i < 8; i++)
#pragma unroll
                for (int j = 0; j < 8; j++) acc[i][j] += a[i] * b[j];
        }
    }

#pragma unroll
    for (int i = 0; i < 8; i++) {
        int row = bM + ty * 8 + i;
        int s = row >> 8, r = row & 255;
#pragma unroll
        for (int j = 0; j < 8; j++) {
            int col = bN + tx * 8 + j;
            int h = col >> 5, d = col & 31;
            float v = acc[i][j];
            if (type == 0) v *= 0.17677669529663687f;  // 1/sqrt(32)
            if (type == 3) v = 1.f / (1.f + __expf(-(v + b_g[col])));
            Out[((s * 8 + h) * 256 + r) * 32 + d] = v;
        }
    }
}

// ---------------------------------------------------------------------------
// Kernel 3: attention per (s, h). 256 threads = 256 queries. K/V resident in
// SMEM; bias staged per 32-key chunk in padded SMEM. Fixed-reference softmax
// (scores bounded; mask -1e9 underflows exp to 0 exactly).
// ---------------------------------------------------------------------------
__global__ void attn_kernel(const float* __restrict__ bias_mask) {
    extern __shared__ float sm[];
    float* Ks = sm;                          // 256*32
    float* Vs = sm + 8192;                   // 256*32
    float* Bb = sm + 16384;                  // 256*33 (padded)
    float* Mb = sm + 16384 + 256 * 33;       // 256

    int s = blockIdx.x, h = blockIdx.y;
    int t = threadIdx.x;

    const float4* Kg = (const float4*)(g_K + (s * 8 + h) * R_DIM * D_DIM);
    const float4* Vg = (const float4*)(g_V + (s * 8 + h) * R_DIM * D_DIM);
#pragma unroll
    for (int i = t; i < 2048; i += 256) {
        ((float4*)Ks)[i] = Kg[i];
        ((float4*)Vs)[i] = Vg[i];
    }
    Mb[t] = (bias_mask[s * 256 + t] - 1.f) * 1e9f;

    float qreg[32];
    const float4* Qg = (const float4*)(g_Q + ((s * 8 + h) * R_DIM + t) * D_DIM);
#pragma unroll
    for (int i = 0; i < 8; i++) {
        float4 v = Qg[i];
        qreg[i * 4 + 0] = v.x; qreg[i * 4 + 1] = v.y;
        qreg[i * 4 + 2] = v.z; qreg[i * 4 + 3] = v.w;
    }

    float l = 0.f;
    float acc[32];
#pragma unroll
    for (int d = 0; d < 32; d++) acc[d] = 0.f;

    const float* biasBase = g_biasT + (h * 256) * 256;

    for (int kc = 0; kc < 256; kc += 32) {
        __syncthreads();
        // stage bias chunk [256 q][32 k] -> Bb[q*33 + k] (conflict-free)
        for (int f = t; f < 2048; f += 256) {
            int qq = f >> 3, k4 = (f & 7) * 4;
            float4 v = *(const float4*)&biasBase[qq * 256 + kc + k4];
            Bb[qq * 33 + k4 + 0] = v.x;
            Bb[qq * 33 + k4 + 1] = v.y;
            Bb[qq * 33 + k4 + 2] = v.z;
            Bb[qq * 33 + k4 + 3] = v.w;
        }
        __syncthreads();
#pragma unroll 4
        for (int kk = 0; kk < 32; kk++) {
            int k = kc + kk;
            const float* Kr = Ks + k * 32;
            float s0 = 0.f, s1 = 0.f, s2 = 0.f, s3 = 0.f;
#pragma unroll
            for (int d = 0; d < 32; d += 4) {
                s0 += qreg[d + 0] * Kr[d + 0];
                s1 += qreg[d + 1] * Kr[d + 1];
                s2 += qreg[d + 2] * Kr[d + 2];
                s3 += qreg[d + 3] * Kr[d + 3];
            }
            float sc = Bb[t * 33 + kk] + Mb[k] + ((s0 + s1) + (s2 + s3));
            float p = __expf(sc);
            l += p;
            const float* Vr = Vs + k * 32;
#pragma unroll
            for (int d = 0; d < 32; d++) acc[d] += p * Vr[d];
        }
    }

    float inv = 1.f / l;
    float* Og = g_O + ((s * 8 + h) * R_DIM + t) * D_DIM;
#pragma unroll
    for (int d = 0; d < 32; d++) Og[d] = acc[d] * inv;
}

// ---------------------------------------------------------------------------
// Kernel 4: out[sr,c] = sum_hd (O*G)[sr,hd] * Wo[hd,c] + b_o[c]
// Same 128x128 SGEMM; A tile formed as O*G on the fly.
// ---------------------------------------------------------------------------
__global__ void outproj_kernel(const float* __restrict__ w_o,
                               const float* __restrict__ b_o,
                               float* __restrict__ out) {
    __shared__ float As[8][128];
    __shared__ float Bs[8][128];
    int t = threadIdx.x;
    int bM = blockIdx.x * 128;
    int bN = blockIdx.y * 128;
    int tx = t & 15, ty = t >> 4;
    int arow = t >> 1, ak = (t & 1) * 4;
    int bk = t >> 5, bcol = (t & 31) * 4;

    float acc[8][8];
#pragma unroll
    for (int i = 0; i < 8; i++)
#pragma unroll
        for (int j = 0; j < 8; j++) acc[i][j] = 0.f;

    int row = bM + arow;
    int s = row >> 8, r = row & 255;

    for (int k0 = 0; k0 < 256; k0 += 8) {
        int hh = k0 >> 5;
        int d0 = (k0 & 31) + ak;  // multiple of 4
        int base = (((s * 8 + hh) * 256 + r) * 32 + d0) >> 2;
        float4 ov = ((const float4*)g_O)[base];
        float4 gv = ((const float4*)g_G)[base];
        float4 av;
        av.x = ov.x * gv.x; av.y = ov.y * gv.y;
        av.z = ov.z * gv.z; av.w = ov.w * gv.w;
        float4 bv = *(const float4*)&w_o[(k0 + bk) * 256 + bN + bcol];
        __syncthreads();
        As[ak + 0][arow] = av.x;
        As[ak + 1][arow] = av.y;
        As[ak + 2][arow] = av.z;
        As[ak + 3][arow] = av.w;
        *(float4*)&Bs[bk][bcol] = bv;
        __syncthreads();
#pragma unroll
        for (int kk = 0; kk < 8; kk++) {
            float4 a0 = *(const float4*)&As[kk][ty * 8];
            float4 a1 = *(const float4*)&As[kk][ty * 8 + 4];
            float4 b0 = *(const float4*)&Bs[kk][tx * 8];
            float4 b1 = *(const float4*)&Bs[kk][tx * 8 + 4];
            float a[8] = {a0.x, a0.y, a0.z, a0.w, a1.x, a1.y, a1.z, a1.w};
            float b[8] = {b0.x, b0.y, b0.z, b0.w, b1.x, b1.y, b1.z, b1.w};
#pragma unroll
            for (int i = 0; i < 8; i++)
#pragma unroll
                for (int j = 0; j < 8; j++) acc[i][j] += a[i] * b[j];
        }
    }

#pragma unroll
    for (int i = 0; i < 8; i++) {
        int orow = bM + ty * 8 + i;
#pragma unroll
        for (int j = 0; j < 8; j++) {
            int col = bN + tx * 8 + j;
            out[orow * 256 + col] = acc[i][j] + b_o[col];
        }
    }
}

// ---------------------------------------------------------------------------
extern "C" void kernel_launch(void* const* d_in, const int* in_sizes, int n_in,
                              void* d_out, int out_size) {
    const float* q    = (const float*)d_in[0];
    const float* kv   = (const float*)d_in[1];
    const float* bias = (const float*)d_in[2];
    const float* mask = (const float*)d_in[3];
    const float* w_q  = (const float*)d_in[4];
    const float* w_k  = (const float*)d_in[5];
    const float* w_v  = (const float*)d_in[6];
    const float* w_g  = (const float*)d_in[7];
    const float* b_g  = (const float*)d_in[8];
    const float* w_o  = (const float*)d_in[9];
    const float* b_o  = (const float*)d_in[10];
    float* out = (float*)d_out;

    bias_transpose_kernel<<<(H_DIM * R_DIM * R_DIM + 255) / 256, 256>>>(bias);

    proj_kernel<<<dim3(SR_DIM / 128, HD_DIM / 128, 4), 256>>>(
        q, kv, w_q, w_k, w_v, w_g, b_g);

    const int ATTN_SMEM = (8192 + 8192 + 256 * 33 + 256) * 4;  // 100352 B
    cudaFuncSetAttribute(attn_kernel,
                         cudaFuncAttributeMaxDynamicSharedMemorySize, ATTN_SMEM);
    attn_kernel<<<dim3(S_DIM, H_DIM), 256, ATTN_SMEM>>>(mask);

    outproj_kernel<<<dim3(SR_DIM / 128, C_DIM / 128), 256>>>(w_o, b_o, out);
}

// round 2
// speedup vs baseline: 1.0113x; 1.0113x over previous
#include <cuda_runtime.h>
#include <math.h>

#define S_DIM 128
#define R_DIM 256
#define C_DIM 256
#define H_DIM 8
#define D_DIM 32
#define HD_DIM 256
#define SR_DIM (S_DIM * R_DIM)

// Scratch (device globals; allocation-free contract)
__device__ float g_Q[S_DIM * H_DIM * R_DIM * D_DIM];   // [s][h][r][d]
__device__ float g_K[S_DIM * H_DIM * R_DIM * D_DIM];
__device__ float g_V[S_DIM * H_DIM * R_DIM * D_DIM];
__device__ float g_G[S_DIM * H_DIM * R_DIM * D_DIM];
__device__ float g_O[S_DIM * H_DIM * R_DIM * D_DIM];
__device__ float g_biasT[H_DIM * R_DIM * R_DIM];       // [h][q][k]

// ---------------------------------------------------------------------------
// Kernel 1: bias [q][k][h] -> biasT [h][q][k]  (makes per-query bias reads
// contiguous in k; bias is s-independent and L2-resident thereafter)
// ---------------------------------------------------------------------------
__global__ void bias_transpose_kernel(const float* __restrict__ bias) {
    int idx = blockIdx.x * blockDim.x + threadIdx.x;
    if (idx < H_DIM * R_DIM * R_DIM) {
        int k  = idx & 255;
        int qq = (idx >> 8) & 255;
        int h  = idx >> 16;
        g_biasT[idx] = bias[((qq << 8) + k) * 8 + h];
    }
}

// ---------------------------------------------------------------------------
// Kernel 2: fused projections. type z: 0=Q(*norm) 1=K 2=V 3=G(sigmoid+b_g)
// C = A[SR,256] * W[256,256], 128x128 tile, k-chunk 8, 8x8 per thread.
// Output layout [s][h][r][d].
// ---------------------------------------------------------------------------
__global__ void proj_kernel(const float* __restrict__ qin,
                            const float* __restrict__ kvin,
                            const float* __restrict__ w_q,
                            const float* __restrict__ w_k,
                            const float* __restrict__ w_v,
                            const float* __restrict__ w_g,
                            const float* __restrict__ b_g) {
    __shared__ float As[8][128];
    __shared__ float Bs[8][128];
    int type = blockIdx.z;
    const float* A = (type == 1 || type == 2) ? kvin : qin;
    const float* W = (type == 0) ? w_q : (type == 1) ? w_k : (type == 2) ? w_v : w_g;
    float* Out = (type == 0) ? g_Q : (type == 1) ? g_K : (type == 2) ? g_V : g_G;

    int t = threadIdx.x;
    int bM = blockIdx.x * 128;
    int bN = blockIdx.y * 128;
    int tx = t & 15, ty = t >> 4;
    int arow = t >> 1, ak = (t & 1) * 4;
    int bk = t >> 5, bcol = (t & 31) * 4;

    float acc[8][8];
#pragma unroll
    for (int i = 0; i < 8; i++)
#pragma unroll
        for (int j = 0; j < 8; j++) acc[i][j] = 0.f;

    for (int k0 = 0; k0 < 256; k0 += 8) {
        float4 av = *(const float4*)&A[(bM + arow) * 256 + k0 + ak];
        float4 bv = *(const float4*)&W[(k0 + bk) * 256 + bN + bcol];
        __syncthreads();
        As[ak + 0][arow] = av.x;
        As[ak + 1][arow] = av.y;
        As[ak + 2][arow] = av.z;
        As[ak + 3][arow] = av.w;
        *(float4*)&Bs[bk][bcol] = bv;
        __syncthreads();
#pragma unroll
        for (int kk = 0; kk < 8; kk++) {
            float4 a0 = *(const float4*)&As[kk][ty * 8];
            float4 a1 = *(const float4*)&As[kk][ty * 8 + 4];
            float4 b0 = *(const float4*)&Bs[kk][tx * 8];
            float4 b1 = *(const float4*)&Bs[kk][tx * 8 + 4];
            float a[8] = {a0.x, a0.y, a0.z, a0.w, a1.x, a1.y, a1.z, a1.w};
            float b[8] = {b0.x, b0.y, b0.z, b0.w, b1.x, b1.y, b1.z, b1.w};
#pragma unroll
            for (int i = 0; i < 8; i++)
#pragma unroll
                for (int j = 0; j < 8; j++) acc[i][j] += a[i] * b[j];
        }
    }

#pragma unroll
    for (int i = 0; i < 8; i++) {
        int row = bM + ty * 8 + i;
        int s = row >> 8, r = row & 255;
#pragma unroll
        for (int j = 0; j < 8; j++) {
            int col = bN + tx * 8 + j;
            int h = col >> 5, d = col & 31;
            float v = acc[i][j];
            if (type == 0) v *= 0.17677669529663687f;  // 1/sqrt(32)
            if (type == 3) v = 1.f / (1.f + __expf(-(v + b_g[col])));
            Out[((s * 8 + h) * 256 + r) * 32 + d] = v;
        }
    }
}

// ---------------------------------------------------------------------------
// Kernel 3: attention per (s, h). 256 threads = 256 queries. K/V resident in
// SMEM; bias staged per 32-key chunk in padded SMEM. Fixed-reference softmax
// (scores bounded; mask -1e9 underflows exp to 0 exactly).
// ---------------------------------------------------------------------------
__global__ void attn_kernel(const float* __restrict__ bias_mask) {
    extern __shared__ float sm[];
    float* Ks = sm;                          // 256*32
    float* Vs = sm + 8192;                   // 256*32
    float* Bb = sm + 16384;                  // 256*33 (padded)
    float* Mb = sm + 16384 + 256 * 33;       // 256

    int s = blockIdx.x, h = blockIdx.y;
    int t = threadIdx.x;

    const float4* Kg = (const float4*)(g_K + (s * 8 + h) * R_DIM * D_DIM);
    const float4* Vg = (const float4*)(g_V + (s * 8 + h) * R_DIM * D_DIM);
#pragma unroll
    for (int i = t; i < 2048; i += 256) {
        ((float4*)Ks)[i] = Kg[i];
        ((float4*)Vs)[i] = Vg[i];
    }
    Mb[t] = (bias_mask[s * 256 + t] - 1.f) * 1e9f;

    float qreg[32];
    const float4* Qg = (const float4*)(g_Q + ((s * 8 + h) * R_DIM + t) * D_DIM);
#pragma unroll
    for (int i = 0; i < 8; i++) {
        float4 v = Qg[i];
        qreg[i * 4 + 0] = v.x; qreg[i * 4 + 1] = v.y;
        qreg[i * 4 + 2] = v.z; qreg[i * 4 + 3] = v.w;
    }

    float l = 0.f;
    float acc[32];
#pragma unroll
    for (int d = 0; d < 32; d++) acc[d] = 0.f;

    const float* biasBase = g_biasT + (h * 256) * 256;

    for (int kc = 0; kc < 256; kc += 32) {
        __syncthreads();
        // stage bias chunk [256 q][32 k] -> Bb[q*33 + k] (conflict-free)
        for (int f = t; f < 2048; f += 256) {
            int qq = f >> 3, k4 = (f & 7) * 4;
            float4 v = *(const float4*)&biasBase[qq * 256 + kc + k4];
            Bb[qq * 33 + k4 + 0] = v.x;
            Bb[qq * 33 + k4 + 1] = v.y;
            Bb[qq * 33 + k4 + 2] = v.z;
            Bb[qq * 33 + k4 + 3] = v.w;
        }
        __syncthreads();
#pragma unroll 4
        for (int kk = 0; kk < 32; kk++) {
            int k = kc + kk;
            const float* Kr = Ks + k * 32;
            float s0 = 0.f, s1 = 0.f, s2 = 0.f, s3 = 0.f;
#pragma unroll
            for (int d = 0; d < 32; d += 4) {
                s0 += qreg[d + 0] * Kr[d + 0];
                s1 += qreg[d + 1] * Kr[d + 1];
                s2 += qreg[d + 2] * Kr[d + 2];
                s3 += qreg[d + 3] * Kr[d + 3];
            }
            float sc = Bb[t * 33 + kk] + Mb[k] + ((s0 + s1) + (s2 + s3));
            float p = __expf(sc);
            l += p;
            const float* Vr = Vs + k * 32;
#pragma unroll
            for (int d = 0; d < 32; d++) acc[d] += p * Vr[d];
        }
    }

    float inv = 1.f / l;
    float* Og = g_O + ((s * 8 + h) * R_DIM + t) * D_DIM;
#pragma unroll
    for (int d = 0; d < 32; d++) Og[d] = acc[d] * inv;
}

// ---------------------------------------------------------------------------
// Kernel 4: out[sr,c] = sum_hd (O*G)[sr,hd] * Wo[hd,c] + b_o[c]
// Same 128x128 SGEMM; A tile formed as O*G on the fly.
// ---------------------------------------------------------------------------
__global__ void outproj_kernel(const float* __restrict__ w_o,
                               const float* __restrict__ b_o,
                               float* __restrict__ out) {
    __shared__ float As[8][128];
    __shared__ float Bs[8][128];
    int t = threadIdx.x;
    int bM = blockIdx.x * 128;
    int bN = blockIdx.y * 128;
    int tx = t & 15, ty = t >> 4;
    int arow = t >> 1, ak = (t & 1) * 4;
    int bk = t >> 5, bcol = (t & 31) * 4;

    float acc[8][8];
#pragma unroll
    for (int i = 0; i < 8; i++)
#pragma unroll
        for (int j = 0; j < 8; j++) acc[i][j] = 0.f;

    int row = bM + arow;
    int s = row >> 8, r = row & 255;

    for (int k0 = 0; k0 < 256; k0 += 8) {
        int hh = k0 >> 5;
        int d0 = (k0 & 31) + ak;  // multiple of 4
        int base = (((s * 8 + hh) * 256 + r) * 32 + d0) >> 2;
        float4 ov = ((const float4*)g_O)[base];
        float4 gv = ((const float4*)g_G)[base];
        float4 av;
        av.x = ov.x * gv.x; av.y = ov.y * gv.y;
        av.z = ov.z * gv.z; av.w = ov.w * gv.w;
        float4 bv = *(const float4*)&w_o[(k0 + bk) * 256 + bN + bcol];
        __syncthreads();
        As[ak + 0][arow] = av.x;
        As[ak + 1][arow] = av.y;
        As[ak + 2][arow] = av.z;
        As[ak + 3][arow] = av.w;
        *(float4*)&Bs[bk][bcol] = bv;
        __syncthreads();
#pragma unroll
        for (int kk = 0; kk < 8; kk++) {
            float4 a0 = *(const float4*)&As[kk][ty * 8];
            float4 a1 = *(const float4*)&As[kk][ty * 8 + 4];
            float4 b0 = *(const float4*)&Bs[kk][tx * 8];
            float4 b1 = *(const float4*)&Bs[kk][tx * 8 + 4];
            float a[8] = {a0.x, a0.y, a0.z, a0.w, a1.x, a1.y, a1.z, a1.w};
            float b[8] = {b0.x, b0.y, b0.z, b0.w, b1.x, b1.y, b1.z, b1.w};
#pragma unroll
            for (int i = 0; i < 8; i++)
#pragma unroll
                for (int j = 0; j < 8; j++) acc[i][j] += a[i] * b[j];
        }
    }

#pragma unroll
    for (int i = 0; i < 8; i++) {
        int orow = bM + ty * 8 + i;
#pragma unroll
        for (int j = 0; j < 8; j++) {
            int col = bN + tx * 8 + j;
            out[orow * 256 + col] = acc[i][j] + b_o[col];
        }
    }
}

// ---------------------------------------------------------------------------
extern "C" void kernel_launch(void* const* d_in, const int* in_sizes, int n_in,
                              void* d_out, int out_size) {
    const float* q    = (const float*)d_in[0];
    const float* kv   = (const float*)d_in[1];
    const float* bias = (const float*)d_in[2];
    const float* mask = (const float*)d_in[3];
    const float* w_q  = (const float*)d_in[4];
    const float* w_k  = (const float*)d_in[5];
    const float* w_v  = (const float*)d_in[6];
    const float* w_g  = (const float*)d_in[7];
    const float* b_g  = (const float*)d_in[8];
    const float* w_o  = (const float*)d_in[9];
    const float* b_o  = (const float*)d_in[10];
    float* out = (float*)d_out;

    bias_transpose_kernel<<<(H_DIM * R_DIM * R_DIM + 255) / 256, 256>>>(bias);

    proj_kernel<<<dim3(SR_DIM / 128, HD_DIM / 128, 4), 256>>>(
        q, kv, w_q, w_k, w_v, w_g, b_g);

    const int ATTN_SMEM = (8192 + 8192 + 256 * 33 + 256) * 4;  // 100352 B
    cudaFuncSetAttribute(attn_kernel,
                         cudaFuncAttributeMaxDynamicSharedMemorySize, ATTN_SMEM);
    attn_kernel<<<dim3(S_DIM, H_DIM), 256, ATTN_SMEM>>>(mask);

    outproj_kernel<<<dim3(SR_DIM / 128, C_DIM / 128), 256>>>(w_o, b_o, out);
}